// round 1
// baseline (speedup 1.0000x reference)
#include <cuda_runtime.h>

// FFT convolution (S4): y[b,0,h,:] = first 4096 samples of linear conv(x[b,h,:], k[0,h,:])
// via length-8192 real FFT implemented as 4096-pt complex FFT with even/odd packing.
//
// Pipeline (3 kernels, stream-ordered, graph-capturable, no allocations):
//   1) init_twiddles: fp64-accurate twiddle tables into __device__ globals
//   2) kf_kernel:     K_f[h][0..4096] = rfft(k[h], 8192)   (1024 CTAs)
//   3) conv_kernel:   per (b,h) row: pack -> DIF fwd FFT -> fused
//                     unpack*K_f*repack (digit-reversed indexing) -> DIT inv FFT -> write
//
// FFT: radix-4, 6 stages, in-place in shared memory with +i/32 padding to kill
// bank conflicts in the small-L stages. DIF forward leaves data digit-reversed
// (base 4); the pointwise multiply works directly in that order via rev4();
// DIT inverse returns natural order. No bit-reversal passes.

#define M 4096            // complex FFT size (real size n = 2*M = 8192)
#define H 1024
#define B 4
#define NTHREADS 512
#define KSTRIDE (M + 1)   // 4097 bins per head
#define PAD(i) ((i) + ((i) >> 5))

__device__ float2 g_twm[M];          // e^{-2pi i e / M}, e = 0..M-1
__device__ float2 g_twn[M / 2 + 1];  // e^{-2pi i k / (2M)}, k = 0..M/2
__device__ float2 g_Kf[H * KSTRIDE]; // half-spectra of kernel rows (natural order)

__device__ __forceinline__ float2 cadd(float2 a, float2 b) { return make_float2(a.x + b.x, a.y + b.y); }
__device__ __forceinline__ float2 csub(float2 a, float2 b) { return make_float2(a.x - b.x, a.y - b.y); }
__device__ __forceinline__ float2 cmul(float2 a, float2 b) {
    return make_float2(fmaf(a.x, b.x, -a.y * b.y), fmaf(a.x, b.y, a.y * b.x));
}
// a * conj(b)
__device__ __forceinline__ float2 cmulc(float2 a, float2 b) {
    return make_float2(fmaf(a.x, b.x, a.y * b.y), fmaf(a.y, b.x, -a.x * b.y));
}

// base-4 digit reversal of a 12-bit index (6 digits)
__device__ __forceinline__ int rev4(int v) {
    unsigned r = __brev((unsigned)v) >> 20;           // 12-bit bit reversal
    return (int)(((r & 0x555u) << 1) | ((r >> 1) & 0x555u)); // swap bit pairs
}

__global__ void init_twiddles() {
    int i = blockIdx.x * blockDim.x + threadIdx.x;
    if (i < M) {
        double s, c;
        sincospi(-2.0 * (double)i / (double)M, &s, &c);
        g_twm[i] = make_float2((float)c, (float)s);
    }
    int j = i - M;
    if (j >= 0 && j <= M / 2) {
        double s, c;
        sincospi(-(double)j / (double)M, &s, &c);     // e^{-2*pi*i*j/(2M)}
        g_twn[j] = make_float2((float)c, (float)s);
    }
}

// ---------------- forward: radix-4 DIF, natural in -> digit-reversed out ----------------
__device__ __forceinline__ void fft_fwd(float2* z, int tid) {
    int L = M;
#pragma unroll
    for (int s = 0; s < 6; s++) {
        const int q = L >> 2;
        const int twstep = M / L;
#pragma unroll
        for (int t = 0; t < (M / 4) / NTHREADS; t++) {
            int i = tid + t * NTHREADS;
            int b = i / q;
            int j = i - b * q;
            int base = b * L + j;
            float2 a0 = z[PAD(base)];
            float2 a1 = z[PAD(base + q)];
            float2 a2 = z[PAD(base + 2 * q)];
            float2 a3 = z[PAD(base + 3 * q)];
            float2 t0 = cadd(a0, a2), t1 = csub(a0, a2);
            float2 t2 = cadd(a1, a3), t3 = csub(a1, a3);
            float2 y0 = cadd(t0, t2);
            float2 y2 = csub(t0, t2);
            float2 y1 = make_float2(t1.x + t3.y, t1.y - t3.x);  // t1 - i*t3
            float2 y3 = make_float2(t1.x - t3.y, t1.y + t3.x);  // t1 + i*t3
            int e = j * twstep;
            float2 w1 = g_twm[e];
            float2 w2 = g_twm[2 * e];
            float2 w3 = g_twm[3 * e];
            z[PAD(base)]         = y0;
            z[PAD(base + q)]     = cmul(y1, w1);
            z[PAD(base + 2 * q)] = cmul(y2, w2);
            z[PAD(base + 3 * q)] = cmul(y3, w3);
        }
        L >>= 2;
        __syncthreads();
    }
}

// ---------------- inverse: radix-4 DIT, digit-reversed in -> natural out (unscaled) -----
__device__ __forceinline__ void fft_inv(float2* z, int tid) {
    int L = 4;
#pragma unroll
    for (int s = 0; s < 6; s++) {
        const int q = L >> 2;
        const int twstep = M / L;
#pragma unroll
        for (int t = 0; t < (M / 4) / NTHREADS; t++) {
            int i = tid + t * NTHREADS;
            int b = i / q;
            int j = i - b * q;
            int base = b * L + j;
            int e = j * twstep;
            float2 w1 = g_twm[e];
            float2 w2 = g_twm[2 * e];
            float2 w3 = g_twm[3 * e];
            float2 b0 = z[PAD(base)];
            float2 b1 = cmulc(z[PAD(base + q)], w1);      // * e^{+2pi i j/L}
            float2 b2 = cmulc(z[PAD(base + 2 * q)], w2);
            float2 b3 = cmulc(z[PAD(base + 3 * q)], w3);
            float2 u0 = cadd(b0, b2), u1 = csub(b0, b2);
            float2 u2 = cadd(b1, b3);
            float2 d  = csub(b1, b3);
            float2 u3 = make_float2(-d.y, d.x);           // +i*(b1-b3)
            z[PAD(base)]         = cadd(u0, u2);
            z[PAD(base + q)]     = cadd(u1, u3);
            z[PAD(base + 2 * q)] = csub(u0, u2);
            z[PAD(base + 3 * q)] = csub(u1, u3);
        }
        L <<= 2;
        __syncthreads();
    }
}

// ---------------- kernel spectra: K_f[h][k] = rfft(k_row zero-padded to 8192) ----------
__global__ __launch_bounds__(NTHREADS) void kf_kernel(const float* __restrict__ kin) {
    __shared__ float2 z[M + M / 32];
    const int h = blockIdx.x;
    const int tid = threadIdx.x;
    const float2* krow = (const float2*)(kin + (size_t)h * M);
    for (int j = tid; j < M / 2; j += NTHREADS) z[PAD(j)] = krow[j];          // pack even/odd
    for (int j = M / 2 + tid; j < M; j += NTHREADS) z[PAD(j)] = make_float2(0.f, 0.f);
    __syncthreads();
    fft_fwd(z, tid);

    float2* Kh = g_Kf + (size_t)h * KSTRIDE;
    for (int kk = tid; kk < M / 2; kk += NTHREADS) {
        if (kk == 0) {
            float2 Z0 = z[PAD(0)];
            Kh[0] = make_float2(Z0.x + Z0.y, 0.f);
            Kh[M] = make_float2(Z0.x - Z0.y, 0.f);
            float2 Zh = z[PAD(2)];               // rev4(M/2) == 2
            Kh[M / 2] = make_float2(Zh.x, -Zh.y); // X[M/2] = conj(Z[M/2])
        } else {
            int p1 = rev4(kk), p2 = rev4(M - kk);
            float2 Zk = z[PAD(p1)], Zm = z[PAD(p2)];
            float2 E = make_float2(0.5f * (Zk.x + Zm.x), 0.5f * (Zk.y - Zm.y));
            float2 D = make_float2(Zk.x - Zm.x, Zk.y + Zm.y);
            float2 O = make_float2(0.5f * D.y, -0.5f * D.x);   // -i*D/2
            float2 OT = cmul(O, g_twn[kk]);
            float2 X1  = cadd(E, OT);                          // X[kk]
            float2 X2c = csub(E, OT);                          // conj(X[M-kk])
            Kh[kk]     = X1;
            Kh[M - kk] = make_float2(X2c.x, -X2c.y);
        }
    }
}

// ---------------- main: per (b,h) row, FFT-convolve with K_f[h] ------------------------
__global__ __launch_bounds__(NTHREADS) void conv_kernel(const float* __restrict__ x,
                                                        float* __restrict__ y) {
    __shared__ float2 z[M + M / 32];
    const int row = blockIdx.x;            // b*H + h
    const int h = row & (H - 1);
    const int tid = threadIdx.x;
    const float2* xrow = (const float2*)(x + (size_t)row * M);
    for (int j = tid; j < M / 2; j += NTHREADS) z[PAD(j)] = xrow[j];
    for (int j = M / 2 + tid; j < M; j += NTHREADS) z[PAD(j)] = make_float2(0.f, 0.f);
    __syncthreads();
    fft_fwd(z, tid);

    const float2* __restrict__ Kh = g_Kf + (size_t)h * KSTRIDE;
    for (int kk = tid; kk < M / 2; kk += NTHREADS) {
        if (kk == 0) {
            // bins 0 and M (both real)
            float2 Z0 = z[PAD(0)];
            float X0 = Z0.x + Z0.y;
            float Xm = Z0.x - Z0.y;
            float2 K0 = Kh[0], Km = Kh[M];
            float2 Y0 = make_float2(X0 * K0.x, X0 * K0.y);
            float2 Ym = make_float2(Xm * Km.x, Xm * Km.y);
            float2 Ey = make_float2(0.5f * (Y0.x + Ym.x), 0.5f * (Y0.y - Ym.y));
            float2 Oy = make_float2(0.5f * (Y0.x - Ym.x), 0.5f * (Y0.y + Ym.y));
            z[PAD(0)] = make_float2(Ey.x - Oy.y, Ey.y + Oy.x);  // Ey + i*Oy
            // bin M/2: Z' = Z * conj(K_f[M/2])
            float2 Zh = z[PAD(2)];
            z[PAD(2)] = cmulc(Zh, Kh[M / 2]);
        } else {
            int p1 = rev4(kk), p2 = rev4(M - kk);
            float2 Zk = z[PAD(p1)], Zm = z[PAD(p2)];
            float2 E = make_float2(0.5f * (Zk.x + Zm.x), 0.5f * (Zk.y - Zm.y));
            float2 D = make_float2(Zk.x - Zm.x, Zk.y + Zm.y);
            float2 O = make_float2(0.5f * D.y, -0.5f * D.x);
            float2 tw = g_twn[kk];
            float2 OT = cmul(O, tw);
            float2 X1  = cadd(E, OT);       // X[kk]
            float2 X2c = csub(E, OT);       // conj(X[M-kk])
            float2 K1 = Kh[kk], K2 = Kh[M - kk];
            float2 Y1  = cmul(X1, K1);                 // Y[kk]
            float2 Y2c = cmulc(X2c, K2);               // conj(Y[M-kk])
            float2 Ey = make_float2(0.5f * (Y1.x + Y2c.x), 0.5f * (Y1.y + Y2c.y));
            float2 G  = make_float2(0.5f * (Y1.x - Y2c.x), 0.5f * (Y1.y - Y2c.y));
            float2 Oy = cmulc(G, tw);                  // e^{+2pi i kk/n} * G
            // Z'[kk] = Ey + i*Oy ; Z'[M-kk] = conj(Ey) + i*conj(Oy)
            z[PAD(p1)] = make_float2(Ey.x - Oy.y, Ey.y + Oy.x);
            z[PAD(p2)] = make_float2(Ey.x + Oy.y, Oy.x - Ey.y);
        }
    }
    __syncthreads();
    fft_inv(z, tid);

    const float scale = 1.0f / (float)M;
    float2* yrow = (float2*)(y + (size_t)row * M);
    for (int j = tid; j < M / 2; j += NTHREADS) {
        float2 v = z[PAD(j)];
        yrow[j] = make_float2(v.x * scale, v.y * scale);  // y[2j], y[2j+1]
    }
}

extern "C" void kernel_launch(void* const* d_in, const int* in_sizes, int n_in,
                              void* d_out, int out_size) {
    const float* x;
    const float* k;
    if (in_sizes[0] == B * H * M) {           // x is the larger tensor
        x = (const float*)d_in[0];
        k = (const float*)d_in[1];
    } else {
        x = (const float*)d_in[1];
        k = (const float*)d_in[0];
    }
    float* y = (float*)d_out;

    init_twiddles<<<(M + M / 2 + 1 + 511) / 512, 512>>>();
    kf_kernel<<<H, NTHREADS>>>(k);
    conv_kernel<<<B * H, NTHREADS>>>(x, y);
}

// round 2
// speedup vs baseline: 1.0051x; 1.0051x over previous
#include <cuda_runtime.h>

// FFT convolution (S4): y[b,0,h,:] = first 4096 samples of linear conv(x[b,h,:], k[0,h,:])
// via length-8192 real FFT implemented as 4096-pt complex FFT with even/odd packing.
//
// Pipeline (3 kernels, stream-ordered, graph-capturable, no allocations):
//   1) init_twiddles: fp64-accurate twiddle tables into __device__ globals
//   2) kf_kernel:     K_f[h][0..4096] = rfft(k[h], 8192)   (1024 CTAs)
//   3) conv_kernel:   per (b,h) row: pack -> DIF fwd FFT -> fused
//                     unpack*K_f*repack (digit-reversed indexing) -> DIT inv FFT -> write
//
// FFT: radix-4, 6 stages, in-place in shared memory with +i/32 padding to kill
// bank conflicts in the small-L stages. DIF forward leaves data digit-reversed
// (base 4); the pointwise multiply works directly in that order via rev4();
// DIT inverse returns natural order. No bit-reversal passes.

#define M 4096            // complex FFT size (real size n = 2*M = 8192)
#define H 1024
#define B 4
#define NTHREADS 512
#define KSTRIDE (M + 1)   // 4097 bins per head
#define PAD(i) ((i) + ((i) >> 5))

__device__ float2 g_twm[M];          // e^{-2pi i e / M}, e = 0..M-1
__device__ float2 g_twn[M / 2 + 1];  // e^{-2pi i k / (2M)}, k = 0..M/2
__device__ float2 g_Kf[H * KSTRIDE]; // half-spectra of kernel rows (natural order)

__device__ __forceinline__ float2 cadd(float2 a, float2 b) { return make_float2(a.x + b.x, a.y + b.y); }
__device__ __forceinline__ float2 csub(float2 a, float2 b) { return make_float2(a.x - b.x, a.y - b.y); }
__device__ __forceinline__ float2 cmul(float2 a, float2 b) {
    return make_float2(fmaf(a.x, b.x, -a.y * b.y), fmaf(a.x, b.y, a.y * b.x));
}
// a * conj(b)
__device__ __forceinline__ float2 cmulc(float2 a, float2 b) {
    return make_float2(fmaf(a.x, b.x, a.y * b.y), fmaf(a.y, b.x, -a.x * b.y));
}

// base-4 digit reversal of a 12-bit index (6 digits)
__device__ __forceinline__ int rev4(int v) {
    unsigned r = __brev((unsigned)v) >> 20;           // 12-bit bit reversal
    return (int)(((r & 0x555u) << 1) | ((r >> 1) & 0x555u)); // swap bit pairs
}

__global__ void init_twiddles() {
    int i = blockIdx.x * blockDim.x + threadIdx.x;
    if (i < M) {
        double s, c;
        sincospi(-2.0 * (double)i / (double)M, &s, &c);
        g_twm[i] = make_float2((float)c, (float)s);
    }
    int j = i - M;
    if (j >= 0 && j <= M / 2) {
        double s, c;
        sincospi(-(double)j / (double)M, &s, &c);     // e^{-2*pi*i*j/(2M)}
        g_twn[j] = make_float2((float)c, (float)s);
    }
}

// ---------------- forward: radix-4 DIF, natural in -> digit-reversed out ----------------
__device__ __forceinline__ void fft_fwd(float2* z, int tid) {
    int L = M;
#pragma unroll
    for (int s = 0; s < 6; s++) {
        const int q = L >> 2;
        const int twstep = M / L;
#pragma unroll
        for (int t = 0; t < (M / 4) / NTHREADS; t++) {
            int i = tid + t * NTHREADS;
            int b = i / q;
            int j = i - b * q;
            int base = b * L + j;
            float2 a0 = z[PAD(base)];
            float2 a1 = z[PAD(base + q)];
            float2 a2 = z[PAD(base + 2 * q)];
            float2 a3 = z[PAD(base + 3 * q)];
            float2 t0 = cadd(a0, a2), t1 = csub(a0, a2);
            float2 t2 = cadd(a1, a3), t3 = csub(a1, a3);
            float2 y0 = cadd(t0, t2);
            float2 y2 = csub(t0, t2);
            float2 y1 = make_float2(t1.x + t3.y, t1.y - t3.x);  // t1 - i*t3
            float2 y3 = make_float2(t1.x - t3.y, t1.y + t3.x);  // t1 + i*t3
            int e = j * twstep;
            float2 w1 = g_twm[e];
            float2 w2 = g_twm[2 * e];
            float2 w3 = g_twm[3 * e];
            z[PAD(base)]         = y0;
            z[PAD(base + q)]     = cmul(y1, w1);
            z[PAD(base + 2 * q)] = cmul(y2, w2);
            z[PAD(base + 3 * q)] = cmul(y3, w3);
        }
        L >>= 2;
        __syncthreads();
    }
}

// ---------------- inverse: radix-4 DIT, digit-reversed in -> natural out (unscaled) -----
__device__ __forceinline__ void fft_inv(float2* z, int tid) {
    int L = 4;
#pragma unroll
    for (int s = 0; s < 6; s++) {
        const int q = L >> 2;
        const int twstep = M / L;
#pragma unroll
        for (int t = 0; t < (M / 4) / NTHREADS; t++) {
            int i = tid + t * NTHREADS;
            int b = i / q;
            int j = i - b * q;
            int base = b * L + j;
            int e = j * twstep;
            float2 w1 = g_twm[e];
            float2 w2 = g_twm[2 * e];
            float2 w3 = g_twm[3 * e];
            float2 b0 = z[PAD(base)];
            float2 b1 = cmulc(z[PAD(base + q)], w1);      // * e^{+2pi i j/L}
            float2 b2 = cmulc(z[PAD(base + 2 * q)], w2);
            float2 b3 = cmulc(z[PAD(base + 3 * q)], w3);
            float2 u0 = cadd(b0, b2), u1 = csub(b0, b2);
            float2 u2 = cadd(b1, b3);
            float2 d  = csub(b1, b3);
            float2 u3 = make_float2(-d.y, d.x);           // +i*(b1-b3)
            z[PAD(base)]         = cadd(u0, u2);
            z[PAD(base + q)]     = cadd(u1, u3);
            z[PAD(base + 2 * q)] = csub(u0, u2);
            z[PAD(base + 3 * q)] = csub(u1, u3);
        }
        L <<= 2;
        __syncthreads();
    }
}

// ---------------- kernel spectra: K_f[h][k] = rfft(k_row zero-padded to 8192) ----------
__global__ __launch_bounds__(NTHREADS) void kf_kernel(const float* __restrict__ kin) {
    __shared__ float2 z[M + M / 32];
    const int h = blockIdx.x;
    const int tid = threadIdx.x;
    const float2* krow = (const float2*)(kin + (size_t)h * M);
    for (int j = tid; j < M / 2; j += NTHREADS) z[PAD(j)] = krow[j];          // pack even/odd
    for (int j = M / 2 + tid; j < M; j += NTHREADS) z[PAD(j)] = make_float2(0.f, 0.f);
    __syncthreads();
    fft_fwd(z, tid);

    float2* Kh = g_Kf + (size_t)h * KSTRIDE;
    for (int kk = tid; kk < M / 2; kk += NTHREADS) {
        if (kk == 0) {
            float2 Z0 = z[PAD(0)];
            Kh[0] = make_float2(Z0.x + Z0.y, 0.f);
            Kh[M] = make_float2(Z0.x - Z0.y, 0.f);
            float2 Zh = z[PAD(2)];               // rev4(M/2) == 2
            Kh[M / 2] = make_float2(Zh.x, -Zh.y); // X[M/2] = conj(Z[M/2])
        } else {
            int p1 = rev4(kk), p2 = rev4(M - kk);
            float2 Zk = z[PAD(p1)], Zm = z[PAD(p2)];
            float2 E = make_float2(0.5f * (Zk.x + Zm.x), 0.5f * (Zk.y - Zm.y));
            float2 D = make_float2(Zk.x - Zm.x, Zk.y + Zm.y);
            float2 O = make_float2(0.5f * D.y, -0.5f * D.x);   // -i*D/2
            float2 OT = cmul(O, g_twn[kk]);
            float2 X1  = cadd(E, OT);                          // X[kk]
            float2 X2c = csub(E, OT);                          // conj(X[M-kk])
            Kh[kk]     = X1;
            Kh[M - kk] = make_float2(X2c.x, -X2c.y);
        }
    }
}

// ---------------- main: per (b,h) row, FFT-convolve with K_f[h] ------------------------
__global__ __launch_bounds__(NTHREADS) void conv_kernel(const float* __restrict__ x,
                                                        float* __restrict__ y) {
    __shared__ float2 z[M + M / 32];
    const int row = blockIdx.x;            // b*H + h
    const int h = row & (H - 1);
    const int tid = threadIdx.x;
    const float2* xrow = (const float2*)(x + (size_t)row * M);
    for (int j = tid; j < M / 2; j += NTHREADS) z[PAD(j)] = xrow[j];
    for (int j = M / 2 + tid; j < M; j += NTHREADS) z[PAD(j)] = make_float2(0.f, 0.f);
    __syncthreads();
    fft_fwd(z, tid);

    const float2* __restrict__ Kh = g_Kf + (size_t)h * KSTRIDE;
    for (int kk = tid; kk < M / 2; kk += NTHREADS) {
        if (kk == 0) {
            // bins 0 and M (both real)
            float2 Z0 = z[PAD(0)];
            float X0 = Z0.x + Z0.y;
            float Xm = Z0.x - Z0.y;
            float2 K0 = Kh[0], Km = Kh[M];
            float2 Y0 = make_float2(X0 * K0.x, X0 * K0.y);
            float2 Ym = make_float2(Xm * Km.x, Xm * Km.y);
            float2 Ey = make_float2(0.5f * (Y0.x + Ym.x), 0.5f * (Y0.y - Ym.y));
            float2 Oy = make_float2(0.5f * (Y0.x - Ym.x), 0.5f * (Y0.y + Ym.y));
            z[PAD(0)] = make_float2(Ey.x - Oy.y, Ey.y + Oy.x);  // Ey + i*Oy
            // bin M/2: Z' = Z * conj(K_f[M/2])
            float2 Zh = z[PAD(2)];
            z[PAD(2)] = cmulc(Zh, Kh[M / 2]);
        } else {
            int p1 = rev4(kk), p2 = rev4(M - kk);
            float2 Zk = z[PAD(p1)], Zm = z[PAD(p2)];
            float2 E = make_float2(0.5f * (Zk.x + Zm.x), 0.5f * (Zk.y - Zm.y));
            float2 D = make_float2(Zk.x - Zm.x, Zk.y + Zm.y);
            float2 O = make_float2(0.5f * D.y, -0.5f * D.x);
            float2 tw = g_twn[kk];
            float2 OT = cmul(O, tw);
            float2 X1  = cadd(E, OT);       // X[kk]
            float2 X2c = csub(E, OT);       // conj(X[M-kk])
            float2 K1 = Kh[kk], K2 = Kh[M - kk];
            float2 Y1  = cmul(X1, K1);                 // Y[kk]
            float2 Y2c = cmulc(X2c, K2);               // conj(Y[M-kk])
            float2 Ey = make_float2(0.5f * (Y1.x + Y2c.x), 0.5f * (Y1.y + Y2c.y));
            float2 G  = make_float2(0.5f * (Y1.x - Y2c.x), 0.5f * (Y1.y - Y2c.y));
            float2 Oy = cmulc(G, tw);                  // e^{+2pi i kk/n} * G
            // Z'[kk] = Ey + i*Oy ; Z'[M-kk] = conj(Ey) + i*conj(Oy)
            z[PAD(p1)] = make_float2(Ey.x - Oy.y, Ey.y + Oy.x);
            z[PAD(p2)] = make_float2(Ey.x + Oy.y, Oy.x - Ey.y);
        }
    }
    __syncthreads();
    fft_inv(z, tid);

    const float scale = 1.0f / (float)M;
    float2* yrow = (float2*)(y + (size_t)row * M);
    for (int j = tid; j < M / 2; j += NTHREADS) {
        float2 v = z[PAD(j)];
        yrow[j] = make_float2(v.x * scale, v.y * scale);  // y[2j], y[2j+1]
    }
}

extern "C" void kernel_launch(void* const* d_in, const int* in_sizes, int n_in,
                              void* d_out, int out_size) {
    const float* x;
    const float* k;
    if (in_sizes[0] == B * H * M) {           // x is the larger tensor
        x = (const float*)d_in[0];
        k = (const float*)d_in[1];
    } else {
        x = (const float*)d_in[1];
        k = (const float*)d_in[0];
    }
    float* y = (float*)d_out;

    init_twiddles<<<(M + M / 2 + 1 + 511) / 512, 512>>>();
    kf_kernel<<<H, NTHREADS>>>(k);
    conv_kernel<<<B * H, NTHREADS>>>(x, y);
}

// round 3
// speedup vs baseline: 2.1100x; 2.0993x over previous
#include <cuda_runtime.h>

// FFT convolution (S4): y[b,0,h,:] = first 4096 samples of linear conv(x[b,h,:], k[0,h,:])
// via length-8192 real FFT implemented as 4096-pt complex FFT with even/odd packing.
//
// R2: radix-8 FFT (4 stages), XOR bank swizzle (conflict-free, no padding),
// one twiddle load per butterfly (powers generated by complex mult),
// 256 threads/CTA, float4 global I/O.

#define M 4096            // complex FFT size (real size n = 2*M = 8192)
#define H 1024
#define B 4
#define NT 256
#define KSTRIDE (M + 1)   // 4097 bins per head

// Bank swizzle: bijection on [0,4096); conflict-free for strides 1/8/64/512 (LDS.64)
#define SW(i) ((i) ^ (((i) >> 3) & 7) ^ ((((i) >> 6) & 3) << 3))

__device__ float2 g_twm[M];          // e^{-2pi i e / M}
__device__ float2 g_twn[M / 2 + 1];  // e^{-2pi i k / (2M)}
__device__ float2 g_Kf[H * KSTRIDE]; // half-spectra of kernel rows (natural order)

__device__ __forceinline__ float2 cadd(float2 a, float2 b) { return make_float2(a.x + b.x, a.y + b.y); }
__device__ __forceinline__ float2 csub(float2 a, float2 b) { return make_float2(a.x - b.x, a.y - b.y); }
__device__ __forceinline__ float2 cmul(float2 a, float2 b) {
    return make_float2(fmaf(a.x, b.x, -a.y * b.y), fmaf(a.x, b.y, a.y * b.x));
}
// a * conj(b)
__device__ __forceinline__ float2 cmulc(float2 a, float2 b) {
    return make_float2(fmaf(a.x, b.x, a.y * b.y), fmaf(a.y, b.x, -a.x * b.y));
}

// base-8 digit reversal of a 12-bit index (4 digits)
__device__ __forceinline__ int rev8(int v) {
    return ((v & 7) << 9) | (((v >> 3) & 7) << 6) | (((v >> 6) & 7) << 3) | ((v >> 9) & 7);
}

__global__ void init_twiddles() {
    int i = blockIdx.x * blockDim.x + threadIdx.x;
    if (i < M) {
        double s, c;
        sincospi(-2.0 * (double)i / (double)M, &s, &c);
        g_twm[i] = make_float2((float)c, (float)s);
    }
    int j = i - M;
    if (j >= 0 && j <= M / 2) {
        double s, c;
        sincospi(-(double)j / (double)M, &s, &c);
        g_twn[j] = make_float2((float)c, (float)s);
    }
}

#define CC 0.70710678118654752f

// One radix-8 stage. FWD: DIF (natural->digit-reversed over the stage sequence
// L = 4096,512,64,8). !FWD: DIT inverse (stage sequence L = 8,64,512,4096).
template <int L, bool FWD>
__device__ __forceinline__ void stage8(float2* __restrict__ z, int tid) {
    constexpr int q = L / 8;
    constexpr int twstep = M / L;
#pragma unroll
    for (int it = 0; it < (M / 8) / NT; it++) {
        int i = tid + it * NT;
        int b = i / q;
        int j = i - b * q;
        int base = b * L + j;

        float2 a0 = z[SW(base + 0 * q)];
        float2 a1 = z[SW(base + 1 * q)];
        float2 a2 = z[SW(base + 2 * q)];
        float2 a3 = z[SW(base + 3 * q)];
        float2 a4 = z[SW(base + 4 * q)];
        float2 a5 = z[SW(base + 5 * q)];
        float2 a6 = z[SW(base + 6 * q)];
        float2 a7 = z[SW(base + 7 * q)];

        if (FWD) {
            // 8-point DFT (w8 = e^{-i pi/4})
            float2 s0 = cadd(a0, a4), s1 = csub(a0, a4), s2 = cadd(a2, a6), s3 = csub(a2, a6);
            float2 E0 = cadd(s0, s2), E2 = csub(s0, s2);
            float2 E1 = make_float2(s1.x + s3.y, s1.y - s3.x);   // s1 - i s3
            float2 E3 = make_float2(s1.x - s3.y, s1.y + s3.x);   // s1 + i s3
            float2 t0 = cadd(a1, a5), t1 = csub(a1, a5), t2 = cadd(a3, a7), t3 = csub(a3, a7);
            float2 O0 = cadd(t0, t2), O2 = csub(t0, t2);
            float2 O1 = make_float2(t1.x + t3.y, t1.y - t3.x);
            float2 O3 = make_float2(t1.x - t3.y, t1.y + t3.x);
            float2 P1 = make_float2(CC * (O1.x + O1.y), CC * (O1.y - O1.x));   // w8^1*O1
            float2 P2 = make_float2(O2.y, -O2.x);                              // w8^2*O2
            float2 P3 = make_float2(CC * (O3.y - O3.x), -CC * (O3.x + O3.y));  // w8^3*O3
            float2 y0 = cadd(E0, O0), y4 = csub(E0, O0);
            float2 y1 = cadd(E1, P1), y5 = csub(E1, P1);
            float2 y2 = cadd(E2, P2), y6 = csub(E2, P2);
            float2 y3 = cadd(E3, P3), y7 = csub(E3, P3);
            if (L > 8) {  // twiddles (L==8 has j==0 -> all ones)
                float2 w1 = g_twm[j * twstep];
                float2 w2 = cmul(w1, w1);
                float2 w3 = cmul(w2, w1);
                float2 w4 = cmul(w2, w2);
                float2 w5 = cmul(w4, w1);
                float2 w6 = cmul(w4, w2);
                float2 w7 = cmul(w4, w3);
                y1 = cmul(y1, w1); y2 = cmul(y2, w2); y3 = cmul(y3, w3);
                y4 = cmul(y4, w4); y5 = cmul(y5, w5); y6 = cmul(y6, w6); y7 = cmul(y7, w7);
            }
            z[SW(base + 0 * q)] = y0;
            z[SW(base + 1 * q)] = y1;
            z[SW(base + 2 * q)] = y2;
            z[SW(base + 3 * q)] = y3;
            z[SW(base + 4 * q)] = y4;
            z[SW(base + 5 * q)] = y5;
            z[SW(base + 6 * q)] = y6;
            z[SW(base + 7 * q)] = y7;
        } else {
            if (L > 8) {  // conjugate twiddles before the butterfly
                float2 w1 = g_twm[j * twstep];
                float2 w2 = cmul(w1, w1);
                float2 w3 = cmul(w2, w1);
                float2 w4 = cmul(w2, w2);
                float2 w5 = cmul(w4, w1);
                float2 w6 = cmul(w4, w2);
                float2 w7 = cmul(w4, w3);
                a1 = cmulc(a1, w1); a2 = cmulc(a2, w2); a3 = cmulc(a3, w3);
                a4 = cmulc(a4, w4); a5 = cmulc(a5, w5); a6 = cmulc(a6, w6); a7 = cmulc(a7, w7);
            }
            // 8-point inverse DFT (v8 = e^{+i pi/4}), unscaled
            float2 s0 = cadd(a0, a4), s1 = csub(a0, a4), s2 = cadd(a2, a6), s3 = csub(a2, a6);
            float2 E0 = cadd(s0, s2), E2 = csub(s0, s2);
            float2 E1 = make_float2(s1.x - s3.y, s1.y + s3.x);   // s1 + i s3
            float2 E3 = make_float2(s1.x + s3.y, s1.y - s3.x);   // s1 - i s3
            float2 t0 = cadd(a1, a5), t1 = csub(a1, a5), t2 = cadd(a3, a7), t3 = csub(a3, a7);
            float2 O0 = cadd(t0, t2), O2 = csub(t0, t2);
            float2 O1 = make_float2(t1.x - t3.y, t1.y + t3.x);
            float2 O3 = make_float2(t1.x + t3.y, t1.y - t3.x);
            float2 P1 = make_float2(CC * (O1.x - O1.y), CC * (O1.x + O1.y));   // v8^1*O1
            float2 P2 = make_float2(-O2.y, O2.x);                              // v8^2*O2
            float2 P3 = make_float2(-CC * (O3.x + O3.y), CC * (O3.x - O3.y));  // v8^3*O3
            float2 u0 = cadd(E0, O0), u4 = csub(E0, O0);
            float2 u1 = cadd(E1, P1), u5 = csub(E1, P1);
            float2 u2 = cadd(E2, P2), u6 = csub(E2, P2);
            float2 u3 = cadd(E3, P3), u7 = csub(E3, P3);
            z[SW(base + 0 * q)] = u0;
            z[SW(base + 1 * q)] = u1;
            z[SW(base + 2 * q)] = u2;
            z[SW(base + 3 * q)] = u3;
            z[SW(base + 4 * q)] = u4;
            z[SW(base + 5 * q)] = u5;
            z[SW(base + 6 * q)] = u6;
            z[SW(base + 7 * q)] = u7;
        }
    }
    __syncthreads();
}

__device__ __forceinline__ void fft_fwd(float2* z, int tid) {
    stage8<4096, true>(z, tid);
    stage8<512, true>(z, tid);
    stage8<64, true>(z, tid);
    stage8<8, true>(z, tid);
}

__device__ __forceinline__ void fft_inv(float2* z, int tid) {
    stage8<8, false>(z, tid);
    stage8<64, false>(z, tid);
    stage8<512, false>(z, tid);
    stage8<4096, false>(z, tid);
}

// ---------------- kernel spectra: K_f[h][k] = rfft(k_row zero-padded to 8192) ----------
__global__ __launch_bounds__(NT, 4) void kf_kernel(const float* __restrict__ kin) {
    __shared__ float2 z[M];
    const int h = blockIdx.x;
    const int tid = threadIdx.x;
    const float4* krow4 = (const float4*)(kin + (size_t)h * M);
    for (int j = tid; j < M / 4; j += NT) {
        float4 v = krow4[j];
        z[SW(2 * j)]     = make_float2(v.x, v.y);
        z[SW(2 * j + 1)] = make_float2(v.z, v.w);
    }
    for (int j = M / 2 + tid; j < M; j += NT) z[SW(j)] = make_float2(0.f, 0.f);
    __syncthreads();
    fft_fwd(z, tid);

    float2* Kh = g_Kf + (size_t)h * KSTRIDE;
    for (int kk = tid; kk < M / 2; kk += NT) {
        if (kk == 0) {
            float2 Z0 = z[SW(0)];
            Kh[0] = make_float2(Z0.x + Z0.y, 0.f);
            Kh[M] = make_float2(Z0.x - Z0.y, 0.f);
            float2 Zh = z[SW(4)];                 // rev8(M/2) == 4
            Kh[M / 2] = make_float2(Zh.x, -Zh.y); // X[M/2] = conj(Z[M/2])
        } else {
            int p1 = SW(rev8(kk)), p2 = SW(rev8(M - kk));
            float2 Zk = z[p1], Zm = z[p2];
            float2 E = make_float2(0.5f * (Zk.x + Zm.x), 0.5f * (Zk.y - Zm.y));
            float2 D = make_float2(Zk.x - Zm.x, Zk.y + Zm.y);
            float2 O = make_float2(0.5f * D.y, -0.5f * D.x);   // -i*D/2
            float2 OT = cmul(O, g_twn[kk]);
            float2 X1  = cadd(E, OT);                          // X[kk]
            float2 X2c = csub(E, OT);                          // conj(X[M-kk])
            Kh[kk]     = X1;
            Kh[M - kk] = make_float2(X2c.x, -X2c.y);
        }
    }
}

// ---------------- main: per (b,h) row, FFT-convolve with K_f[h] ------------------------
__global__ __launch_bounds__(NT, 4) void conv_kernel(const float* __restrict__ x,
                                                     float* __restrict__ y) {
    __shared__ float2 z[M];
    const int row = blockIdx.x;            // b*H + h
    const int h = row & (H - 1);
    const int tid = threadIdx.x;
    const float4* xrow4 = (const float4*)(x + (size_t)row * M);
    for (int j = tid; j < M / 4; j += NT) {
        float4 v = xrow4[j];
        z[SW(2 * j)]     = make_float2(v.x, v.y);
        z[SW(2 * j + 1)] = make_float2(v.z, v.w);
    }
    for (int j = M / 2 + tid; j < M; j += NT) z[SW(j)] = make_float2(0.f, 0.f);
    __syncthreads();
    fft_fwd(z, tid);

    const float2* __restrict__ Kh = g_Kf + (size_t)h * KSTRIDE;
    for (int kk = tid; kk < M / 2; kk += NT) {
        if (kk == 0) {
            // bins 0 and M (both real)
            float2 Z0 = z[SW(0)];
            float X0 = Z0.x + Z0.y;
            float Xm = Z0.x - Z0.y;
            float2 K0 = Kh[0], Km = Kh[M];
            float2 Y0 = make_float2(X0 * K0.x, X0 * K0.y);
            float2 Ym = make_float2(Xm * Km.x, Xm * Km.y);
            float2 Ey = make_float2(0.5f * (Y0.x + Ym.x), 0.5f * (Y0.y - Ym.y));
            float2 Oy = make_float2(0.5f * (Y0.x - Ym.x), 0.5f * (Y0.y + Ym.y));
            z[SW(0)] = make_float2(Ey.x - Oy.y, Ey.y + Oy.x);  // Ey + i*Oy
            // bin M/2: Z' = Z * conj(K_f[M/2])
            float2 Zh = z[SW(4)];
            z[SW(4)] = cmulc(Zh, Kh[M / 2]);
        } else {
            int p1 = SW(rev8(kk)), p2 = SW(rev8(M - kk));
            float2 Zk = z[p1], Zm = z[p2];
            float2 E = make_float2(0.5f * (Zk.x + Zm.x), 0.5f * (Zk.y - Zm.y));
            float2 D = make_float2(Zk.x - Zm.x, Zk.y + Zm.y);
            float2 O = make_float2(0.5f * D.y, -0.5f * D.x);
            float2 tw = g_twn[kk];
            float2 OT = cmul(O, tw);
            float2 X1  = cadd(E, OT);       // X[kk]
            float2 X2c = csub(E, OT);       // conj(X[M-kk])
            float2 K1 = Kh[kk], K2 = Kh[M - kk];
            float2 Y1  = cmul(X1, K1);                 // Y[kk]
            float2 Y2c = cmulc(X2c, K2);               // conj(Y[M-kk])
            float2 Ey = make_float2(0.5f * (Y1.x + Y2c.x), 0.5f * (Y1.y + Y2c.y));
            float2 G  = make_float2(0.5f * (Y1.x - Y2c.x), 0.5f * (Y1.y - Y2c.y));
            float2 Oy = cmulc(G, tw);                  // e^{+2pi i kk/n} * G
            // Z'[kk] = Ey + i*Oy ; Z'[M-kk] = conj(Ey) + i*conj(Oy)
            z[p1] = make_float2(Ey.x - Oy.y, Ey.y + Oy.x);
            z[p2] = make_float2(Ey.x + Oy.y, Oy.x - Ey.y);
        }
    }
    __syncthreads();
    fft_inv(z, tid);

    const float scale = 1.0f / (float)M;
    float4* yrow4 = (float4*)(y + (size_t)row * M);
    for (int j = tid; j < M / 4; j += NT) {
        float2 v0 = z[SW(2 * j)];
        float2 v1 = z[SW(2 * j + 1)];
        yrow4[j] = make_float4(v0.x * scale, v0.y * scale, v1.x * scale, v1.y * scale);
    }
}

extern "C" void kernel_launch(void* const* d_in, const int* in_sizes, int n_in,
                              void* d_out, int out_size) {
    const float* x;
    const float* k;
    if (in_sizes[0] == B * H * M) {           // x is the larger tensor
        x = (const float*)d_in[0];
        k = (const float*)d_in[1];
    } else {
        x = (const float*)d_in[1];
        k = (const float*)d_in[0];
    }
    float* y = (float*)d_out;

    init_twiddles<<<(M + M / 2 + 1 + 511) / 512, 512>>>();
    kf_kernel<<<H, NT>>>(k);
    conv_kernel<<<B * H, NT>>>(x, y);
}

// round 4
// speedup vs baseline: 2.8199x; 1.3365x over previous
#include <cuda_runtime.h>

// FFT convolution (S4): y[b,0,h,:] = first 4096 samples of linear conv(x[b,h,:], k[0,h,:])
// via length-8192 real FFT implemented as 4096-pt complex FFT with even/odd packing.
//
// R3: conflict-free pointwise pass (position-domain iteration, partner p2 = 4607-p,
// position-major K_f layout, pre-permuted twn table), zero-input pruning of the first
// forward stage, discarded-output pruning of the last inverse stage, fp32 twiddle init.

#define M 4096            // complex FFT size (real size n = 2*M = 8192)
#define H 1024
#define B 4
#define NT 256
#define KSTRIDE (M + 1)   // 4096 position-major bins + bin M

// Bank swizzle: bijection on [0,4096); conflict-free for strides 1/8/64/512 (LDS.64)
#define SW(i) ((i) ^ (((i) >> 3) & 7) ^ ((((i) >> 6) & 3) << 3))

__device__ float2 g_twm[M];            // e^{-2pi i e / M}
__device__ float2 g_twnR[M / 2];       // twn[rev8(expand(t))], t = 0..2047
__device__ float2 g_Kf[H * KSTRIDE];   // position-major: g_Kf[h][p] = K_f[h][rev8(p)]; [4096] = bin M

__device__ __forceinline__ float2 cadd(float2 a, float2 b) { return make_float2(a.x + b.x, a.y + b.y); }
__device__ __forceinline__ float2 csub(float2 a, float2 b) { return make_float2(a.x - b.x, a.y - b.y); }
__device__ __forceinline__ float2 cmul(float2 a, float2 b) {
    return make_float2(fmaf(a.x, b.x, -a.y * b.y), fmaf(a.x, b.y, a.y * b.x));
}
// a * conj(b)
__device__ __forceinline__ float2 cmulc(float2 a, float2 b) {
    return make_float2(fmaf(a.x, b.x, a.y * b.y), fmaf(a.y, b.x, -a.x * b.y));
}

// base-8 digit reversal of a 12-bit index (4 digits)
__device__ __forceinline__ int rev8(int v) {
    return ((v & 7) << 9) | (((v >> 3) & 7) << 6) | (((v >> 6) & 7) << 3) | ((v >> 9) & 7);
}
// insert a 0 at bit 2: primary positions (kk < 2048 <=> p&4 == 0)
__device__ __forceinline__ int expandp(int t) { return (t & 3) | ((t >> 2) << 3); }

__global__ void init_twiddles() {
    int i = blockIdx.x * blockDim.x + threadIdx.x;
    if (i < M) {
        float s, c;
        sincospif(-2.0f * (float)i / (float)M, &s, &c);
        g_twm[i] = make_float2(c, s);
    }
    int t = i - M;
    if (t >= 0 && t < M / 2) {
        int kk = rev8(expandp(t));
        float s, c;
        sincospif(-(float)kk / (float)M, &s, &c);   // e^{-2 pi i kk / (2M)}
        g_twnR[t] = make_float2(c, s);
    }
}

#define CC 0.70710678118654752f

// One radix-8 stage. FWD: DIF (L = 4096,512,64,8). !FWD: DIT inverse (L = 8,64,512,4096).
// PIN:  (fwd, L=4096 only) inputs at indices >= 2048 are zero and are not loaded.
// POUT: (inv, L=4096 only) outputs at indices >= 2048 are discarded and not stored.
template <int L, bool FWD, bool PIN = false, bool POUT = false>
__device__ __forceinline__ void stage8(float2* __restrict__ z, int tid) {
    constexpr int q = L / 8;
    constexpr int twstep = M / L;
#pragma unroll
    for (int it = 0; it < (M / 8) / NT; it++) {
        int i = tid + it * NT;
        int b = i / q;
        int j = i - b * q;
        int base = b * L + j;

        float2 a0 = z[SW(base + 0 * q)];
        float2 a1 = z[SW(base + 1 * q)];
        float2 a2 = z[SW(base + 2 * q)];
        float2 a3 = z[SW(base + 3 * q)];
        float2 a4, a5, a6, a7;
        if (!PIN) {
            a4 = z[SW(base + 4 * q)];
            a5 = z[SW(base + 5 * q)];
            a6 = z[SW(base + 6 * q)];
            a7 = z[SW(base + 7 * q)];
        }

        if (FWD) {
            float2 E0, E1, E2, E3, O0, O1, O2, O3;
            if (PIN) {
                // a4..a7 == 0
                E0 = cadd(a0, a2);
                E2 = csub(a0, a2);
                E1 = make_float2(a0.x + a2.y, a0.y - a2.x);   // a0 - i a2
                E3 = make_float2(a0.x - a2.y, a0.y + a2.x);   // a0 + i a2
                O0 = cadd(a1, a3);
                O2 = csub(a1, a3);
                O1 = make_float2(a1.x + a3.y, a1.y - a3.x);
                O3 = make_float2(a1.x - a3.y, a1.y + a3.x);
            } else {
                float2 s0 = cadd(a0, a4), s1 = csub(a0, a4), s2 = cadd(a2, a6), s3 = csub(a2, a6);
                E0 = cadd(s0, s2); E2 = csub(s0, s2);
                E1 = make_float2(s1.x + s3.y, s1.y - s3.x);   // s1 - i s3
                E3 = make_float2(s1.x - s3.y, s1.y + s3.x);   // s1 + i s3
                float2 t0 = cadd(a1, a5), t1 = csub(a1, a5), t2 = cadd(a3, a7), t3 = csub(a3, a7);
                O0 = cadd(t0, t2); O2 = csub(t0, t2);
                O1 = make_float2(t1.x + t3.y, t1.y - t3.x);
                O3 = make_float2(t1.x - t3.y, t1.y + t3.x);
            }
            float2 P1 = make_float2(CC * (O1.x + O1.y), CC * (O1.y - O1.x));   // w8^1*O1
            float2 P2 = make_float2(O2.y, -O2.x);                              // w8^2*O2
            float2 P3 = make_float2(CC * (O3.y - O3.x), -CC * (O3.x + O3.y));  // w8^3*O3
            float2 y0 = cadd(E0, O0), y4 = csub(E0, O0);
            float2 y1 = cadd(E1, P1), y5 = csub(E1, P1);
            float2 y2 = cadd(E2, P2), y6 = csub(E2, P2);
            float2 y3 = cadd(E3, P3), y7 = csub(E3, P3);
            if (L > 8) {  // twiddles (L==8 has j==0 -> all ones)
                float2 w1 = g_twm[j * twstep];
                float2 w2 = cmul(w1, w1);
                float2 w3 = cmul(w2, w1);
                float2 w4 = cmul(w2, w2);
                float2 w5 = cmul(w4, w1);
                float2 w6 = cmul(w4, w2);
                float2 w7 = cmul(w4, w3);
                y1 = cmul(y1, w1); y2 = cmul(y2, w2); y3 = cmul(y3, w3);
                y4 = cmul(y4, w4); y5 = cmul(y5, w5); y6 = cmul(y6, w6); y7 = cmul(y7, w7);
            }
            z[SW(base + 0 * q)] = y0;
            z[SW(base + 1 * q)] = y1;
            z[SW(base + 2 * q)] = y2;
            z[SW(base + 3 * q)] = y3;
            z[SW(base + 4 * q)] = y4;
            z[SW(base + 5 * q)] = y5;
            z[SW(base + 6 * q)] = y6;
            z[SW(base + 7 * q)] = y7;
        } else {
            if (L > 8) {  // conjugate twiddles before the butterfly
                float2 w1 = g_twm[j * twstep];
                float2 w2 = cmul(w1, w1);
                float2 w3 = cmul(w2, w1);
                float2 w4 = cmul(w2, w2);
                float2 w5 = cmul(w4, w1);
                float2 w6 = cmul(w4, w2);
                float2 w7 = cmul(w4, w3);
                a1 = cmulc(a1, w1); a2 = cmulc(a2, w2); a3 = cmulc(a3, w3);
                a4 = cmulc(a4, w4); a5 = cmulc(a5, w5); a6 = cmulc(a6, w6); a7 = cmulc(a7, w7);
            }
            float2 s0 = cadd(a0, a4), s1 = csub(a0, a4), s2 = cadd(a2, a6), s3 = csub(a2, a6);
            float2 E0 = cadd(s0, s2), E2 = csub(s0, s2);
            float2 E1 = make_float2(s1.x - s3.y, s1.y + s3.x);   // s1 + i s3
            float2 E3 = make_float2(s1.x + s3.y, s1.y - s3.x);   // s1 - i s3
            float2 t0 = cadd(a1, a5), t1 = csub(a1, a5), t2 = cadd(a3, a7), t3 = csub(a3, a7);
            float2 O0 = cadd(t0, t2), O2 = csub(t0, t2);
            float2 O1 = make_float2(t1.x - t3.y, t1.y + t3.x);
            float2 O3 = make_float2(t1.x + t3.y, t1.y - t3.x);
            float2 P1 = make_float2(CC * (O1.x - O1.y), CC * (O1.x + O1.y));   // v8^1*O1
            float2 P2 = make_float2(-O2.y, O2.x);                              // v8^2*O2
            float2 P3 = make_float2(-CC * (O3.x + O3.y), CC * (O3.x - O3.y));  // v8^3*O3
            z[SW(base + 0 * q)] = cadd(E0, O0);
            z[SW(base + 1 * q)] = cadd(E1, P1);
            z[SW(base + 2 * q)] = cadd(E2, P2);
            z[SW(base + 3 * q)] = cadd(E3, P3);
            if (!POUT) {
                z[SW(base + 4 * q)] = csub(E0, O0);
                z[SW(base + 5 * q)] = csub(E1, P1);
                z[SW(base + 6 * q)] = csub(E2, P2);
                z[SW(base + 7 * q)] = csub(E3, P3);
            }
        }
    }
    __syncthreads();
}

__device__ __forceinline__ void fft_fwd(float2* z, int tid) {
    stage8<4096, true, true>(z, tid);   // upper half of input is zero
    stage8<512, true>(z, tid);
    stage8<64, true>(z, tid);
    stage8<8, true>(z, tid);
}

__device__ __forceinline__ void fft_inv(float2* z, int tid) {
    stage8<8, false>(z, tid);
    stage8<64, false>(z, tid);
    stage8<512, false>(z, tid);
    stage8<4096, false, false, true>(z, tid);  // upper half of output discarded
}

// load packed real row (x[2j], x[2j+1]) -> z[j]; upper half left untouched (pruned)
__device__ __forceinline__ void load_packed(float2* z, const float* src, int tid) {
    const float4* s4 = (const float4*)src;
    for (int j = tid; j < M / 4; j += NT) {
        float4 v = s4[j];
        z[SW(2 * j)]     = make_float2(v.x, v.y);
        z[SW(2 * j + 1)] = make_float2(v.z, v.w);
    }
    __syncthreads();
}

// ---------------- kernel spectra (position-major layout) -------------------------------
__global__ __launch_bounds__(NT, 4) void kf_kernel(const float* __restrict__ kin) {
    __shared__ float2 z[M];
    const int h = blockIdx.x;
    const int tid = threadIdx.x;
    load_packed(z, kin + (size_t)h * M, tid);
    fft_fwd(z, tid);

    float2* Kh = g_Kf + (size_t)h * KSTRIDE;
    // boundary: kk ≡ 0 (mod 8)  (positions p < 512)
    {
        int t = tid;
        if (t == 0) {
            float2 Z0 = z[0];                      // SW(0)==0
            Kh[0]    = make_float2(Z0.x + Z0.y, 0.f);   // K_f[0]
            Kh[M]    = make_float2(Z0.x - Z0.y, 0.f);   // K_f[M]
            float2 Zh = z[SW(4)];                  // rev8(2048)==4
            Kh[4] = make_float2(Zh.x, -Zh.y);      // K_f[M/2] = conj(Z[M/2])
        } else {
            int kk = 8 * t;
            int pa = rev8(kk), pb = rev8(M - kk);
            float2 Zk = z[SW(pa)], Zm = z[SW(pb)];
            float2 E = make_float2(0.5f * (Zk.x + Zm.x), 0.5f * (Zk.y - Zm.y));
            float2 D = make_float2(Zk.x - Zm.x, Zk.y + Zm.y);
            float2 O = make_float2(0.5f * D.y, -0.5f * D.x);
            float2 OT = cmul(O, g_twm[4 * t]);     // twn[8t] == g_twm[4t]
            float2 X1  = cadd(E, OT);
            float2 X2c = csub(E, OT);
            Kh[pa] = X1;                           // K_f[kk]
            Kh[pb] = make_float2(X2c.x, -X2c.y);   // K_f[M-kk]
        }
    }
    // main: positions p >= 512, partner p2 = 4607 - p (conflict-free)
#pragma unroll
    for (int i2 = 1; i2 < 8; i2++) {
        int t = tid + i2 * NT;
        int p = expandp(t);
        int p2 = 4607 - p;
        float2 Zk = z[SW(p)], Zm = z[SW(p2)];
        float2 E = make_float2(0.5f * (Zk.x + Zm.x), 0.5f * (Zk.y - Zm.y));
        float2 D = make_float2(Zk.x - Zm.x, Zk.y + Zm.y);
        float2 O = make_float2(0.5f * D.y, -0.5f * D.x);
        float2 OT = cmul(O, g_twnR[t]);
        float2 X1  = cadd(E, OT);
        float2 X2c = csub(E, OT);
        Kh[p]  = X1;
        Kh[p2] = make_float2(X2c.x, -X2c.y);
    }
}

// ---------------- main conv ------------------------------------------------------------
__global__ __launch_bounds__(NT, 4) void conv_kernel(const float* __restrict__ x,
                                                     float* __restrict__ y) {
    __shared__ float2 z[M];
    const int row = blockIdx.x;            // b*H + h
    const int h = row & (H - 1);
    const int tid = threadIdx.x;
    load_packed(z, x + (size_t)row * M, tid);
    fft_fwd(z, tid);

    const float2* __restrict__ Kh = g_Kf + (size_t)h * KSTRIDE;
    // boundary: kk ≡ 0 (mod 8)
    {
        int t = tid;
        if (t == 0) {
            float2 Z0 = z[0];
            float X0 = Z0.x + Z0.y;
            float Xm = Z0.x - Z0.y;
            float2 K0 = Kh[0], Km = Kh[M];
            float2 Y0 = make_float2(X0 * K0.x, X0 * K0.y);
            float2 Ym = make_float2(Xm * Km.x, Xm * Km.y);
            float2 Ey = make_float2(0.5f * (Y0.x + Ym.x), 0.5f * (Y0.y - Ym.y));
            float2 Oy = make_float2(0.5f * (Y0.x - Ym.x), 0.5f * (Y0.y + Ym.y));
            z[0] = make_float2(Ey.x - Oy.y, Ey.y + Oy.x);  // Ey + i*Oy
            float2 Zh = z[SW(4)];
            z[SW(4)] = cmulc(Zh, Kh[4]);                    // bin M/2
        } else {
            int kk = 8 * t;
            int pa = rev8(kk), pb = rev8(M - kk);
            int spa = SW(pa), spb = SW(pb);
            float2 Zk = z[spa], Zm = z[spb];
            float2 tw = g_twm[4 * t];
            float2 E = make_float2(0.5f * (Zk.x + Zm.x), 0.5f * (Zk.y - Zm.y));
            float2 D = make_float2(Zk.x - Zm.x, Zk.y + Zm.y);
            float2 O = make_float2(0.5f * D.y, -0.5f * D.x);
            float2 OT = cmul(O, tw);
            float2 X1  = cadd(E, OT);
            float2 X2c = csub(E, OT);
            float2 K1 = Kh[pa], K2 = Kh[pb];
            float2 Y1  = cmul(X1, K1);
            float2 Y2c = cmulc(X2c, K2);
            float2 Ey = make_float2(0.5f * (Y1.x + Y2c.x), 0.5f * (Y1.y + Y2c.y));
            float2 G  = make_float2(0.5f * (Y1.x - Y2c.x), 0.5f * (Y1.y - Y2c.y));
            float2 Oy = cmulc(G, tw);
            z[spa] = make_float2(Ey.x - Oy.y, Ey.y + Oy.x);
            z[spb] = make_float2(Ey.x + Oy.y, Oy.x - Ey.y);
        }
    }
    // main: conflict-free positions
#pragma unroll
    for (int i2 = 1; i2 < 8; i2++) {
        int t = tid + i2 * NT;
        int p = expandp(t);
        int p2 = 4607 - p;
        int sp = SW(p), sp2 = SW(p2);
        float2 Zk = z[sp], Zm = z[sp2];
        float2 tw = g_twnR[t];
        float2 E = make_float2(0.5f * (Zk.x + Zm.x), 0.5f * (Zk.y - Zm.y));
        float2 D = make_float2(Zk.x - Zm.x, Zk.y + Zm.y);
        float2 O = make_float2(0.5f * D.y, -0.5f * D.x);
        float2 OT = cmul(O, tw);
        float2 X1  = cadd(E, OT);
        float2 X2c = csub(E, OT);
        float2 K1 = Kh[p], K2 = Kh[p2];
        float2 Y1  = cmul(X1, K1);
        float2 Y2c = cmulc(X2c, K2);
        float2 Ey = make_float2(0.5f * (Y1.x + Y2c.x), 0.5f * (Y1.y + Y2c.y));
        float2 G  = make_float2(0.5f * (Y1.x - Y2c.x), 0.5f * (Y1.y - Y2c.y));
        float2 Oy = cmulc(G, tw);
        z[sp]  = make_float2(Ey.x - Oy.y, Ey.y + Oy.x);
        z[sp2] = make_float2(Ey.x + Oy.y, Oy.x - Ey.y);
    }
    __syncthreads();
    fft_inv(z, tid);

    const float scale = 1.0f / (float)M;
    float4* yrow4 = (float4*)(y + (size_t)row * M);
    for (int j = tid; j < M / 4; j += NT) {
        float2 v0 = z[SW(2 * j)];
        float2 v1 = z[SW(2 * j + 1)];
        yrow4[j] = make_float4(v0.x * scale, v0.y * scale, v1.x * scale, v1.y * scale);
    }
}

extern "C" void kernel_launch(void* const* d_in, const int* in_sizes, int n_in,
                              void* d_out, int out_size) {
    const float* x;
    const float* k;
    if (in_sizes[0] == B * H * M) {           // x is the larger tensor
        x = (const float*)d_in[0];
        k = (const float*)d_in[1];
    } else {
        x = (const float*)d_in[1];
        k = (const float*)d_in[0];
    }
    float* y = (float*)d_out;

    init_twiddles<<<(M + M / 2 + 511) / 512, 512>>>();
    kf_kernel<<<H, NT>>>(k);
    conv_kernel<<<B * H, NT>>>(x, y);
}